// round 13
// baseline (speedup 1.0000x reference)
#include <cuda_runtime.h>
#include <math.h>

#define B_   4
#define S_   2048
#define N_   2049
#define D_   512
#define R_   64
#define L_   2
#define WINW 32
#define E_   66      // 65 window edges + anchor
#define M_   (B_*N_)
#define SCALE 0.125f

// ---------------- scratch (no allocs allowed) ----------------
__device__ float g_val[M_*D_];
__device__ float g_dval[M_*D_];
__device__ float g_q[M_*R_];
__device__ float g_k[M_*R_];
__device__ float g_we[M_*E_];
__device__ float g_state[M_];
__device__ float g_dstate[M_];

// ---------------- packed f32x2 helpers (Blackwell FFMA2) ----------------
__device__ __forceinline__ unsigned long long pk2(float x, float y) {
    unsigned long long r;
    asm("mov.b64 %0, {%1, %2};" : "=l"(r) : "f"(x), "f"(y));
    return r;
}
__device__ __forceinline__ void fma2(unsigned long long& d, unsigned long long a,
                                     unsigned long long b, unsigned long long c) {
    asm("fma.rn.f32x2 %0, %1, %2, %3;" : "=l"(d) : "l"(a), "l"(b), "l"(c));
}
__device__ __forceinline__ void upk2(float& x, float& y, unsigned long long v) {
    asm("mov.b64 {%0, %1}, %2;" : "=f"(x), "=f"(y) : "l"(v));
}

// ---------------- block reduction (256 threads) ----------------
__device__ __forceinline__ float blkSum256(float v, float* sh) {
    int lane = threadIdx.x & 31, w = threadIdx.x >> 5;
    #pragma unroll
    for (int o = 16; o; o >>= 1) v += __shfl_xor_sync(0xffffffffu, v, o);
    if (lane == 0) sh[w] = v;
    __syncthreads();
    if (w == 0) {
        float x = (lane < 8) ? sh[lane] : 0.f;
        #pragma unroll
        for (int o = 4; o; o >>= 1) x += __shfl_xor_sync(0xffffffffu, x, o);
        if (lane == 0) sh[0] = x;
    }
    __syncthreads();
    float r = sh[0];
    __syncthreads();
    return r;
}

// ---------------- K1: embedding + input LN + state proj ----------------
__global__ void k_embed(const int* __restrict__ ids, const float* __restrict__ emb,
                        const float* __restrict__ pos, const float* __restrict__ aval,
                        const float* __restrict__ ast,
                        const float* __restrict__ ing, const float* __restrict__ inb,
                        const float* __restrict__ spw, const float* __restrict__ spb) {
    __shared__ float sh[8];
    int bn = blockIdx.x;
    int b = bn / N_, n = bn % N_;
    float* vrow = g_val + (size_t)bn * D_;
    int t = threadIdx.x;
    if (n == 0) {
        vrow[t]       = aval[t];
        vrow[t + 256] = aval[t + 256];
        if (t == 0) g_state[bn] = ast[0];
        return;
    }
    int id = ids[b * S_ + (n - 1)];
    float x0 = emb[(size_t)id * D_ + t]       + pos[(size_t)(n - 1) * D_ + t];
    float x1 = emb[(size_t)id * D_ + t + 256] + pos[(size_t)(n - 1) * D_ + t + 256];
    float m  = blkSum256(x0 + x1, sh) * (1.f / D_);
    float d0 = x0 - m, d1 = x1 - m;
    float var = blkSum256(d0 * d0 + d1 * d1, sh) * (1.f / D_);
    float inv = rsqrtf(var + 1e-5f);
    float y0 = d0 * inv * ing[t]       + inb[t];
    float y1 = d1 * inv * ing[t + 256] + inb[t + 256];
    vrow[t] = y0; vrow[t + 256] = y1;
    float dp = blkSum256(y0 * spw[t] + y1 * spw[t + 256], sh);
    if (t == 0) g_state[bn] = dp + spb[0];
}

// ---------------- K2: q/k projection  [M,512] @ [512,128], FFMA2 ----------------
// 256 threads, 32-row x 128-col tile, thread = 2 rows x (4 q-cols + 4 k-cols)
__global__ __launch_bounds__(256) void k_proj(const float* __restrict__ wq,
                                              const float* __restrict__ wk, int layer) {
    __shared__ float As[32][36];    // [row][kk]
    __shared__ float Bs[32][132];   // [kk][col] cols 0..63=q, 64..127=k
    int m0 = blockIdx.x * 32;
    const float* wqL = wq + (size_t)layer * D_ * R_;
    const float* wkL = wk + (size_t)layer * D_ * R_;
    int t  = threadIdx.x;
    int cg = t & 15;     // q cols cg*4.., k cols 64+cg*4..
    int rg = t >> 4;     // 2 rows each (rg 0..15)
    unsigned long long q01[2], q23[2], k01[2], k23[2];
    #pragma unroll
    for (int i = 0; i < 2; i++) { q01[i] = 0ull; q23[i] = 0ull; k01[i] = 0ull; k23[i] = 0ull; }

    for (int kc = 0; kc < D_; kc += 32) {
        // As: 32 rows x 32 k = 256 float4, one per thread
        {
            int row = t >> 3, kq = (t & 7) * 4;
            int gr = m0 + row; if (gr >= M_) gr = M_ - 1;
            float4 v = *(const float4*)&g_val[(size_t)gr * D_ + kc + kq];
            *(float4*)&As[row][kq] = v;
        }
        // Bs: 32 k x 128 cols = 1024 float4, 4 per thread
        #pragma unroll
        for (int i = t; i < 32 * 32; i += 256) {
            int kk = i >> 5, c4 = (i & 31) * 4;
            float4 v;
            if (c4 < 64) v = *(const float4*)&wqL[(size_t)(kc + kk) * R_ + c4];
            else         v = *(const float4*)&wkL[(size_t)(kc + kk) * R_ + (c4 - 64)];
            *(float4*)&Bs[kk][c4] = v;
        }
        __syncthreads();
        #pragma unroll 8
        for (int kk = 0; kk < 32; kk++) {
            unsigned long long ap[2];
            #pragma unroll
            for (int i = 0; i < 2; i++) {
                float av = As[rg * 2 + i][kk];
                ap[i] = pk2(av, av);
            }
            ulonglong2 bq = *(const ulonglong2*)&Bs[kk][cg * 4];
            ulonglong2 bk = *(const ulonglong2*)&Bs[kk][64 + cg * 4];
            #pragma unroll
            for (int i = 0; i < 2; i++) {
                fma2(q01[i], ap[i], bq.x, q01[i]);
                fma2(q23[i], ap[i], bq.y, q23[i]);
                fma2(k01[i], ap[i], bk.x, k01[i]);
                fma2(k23[i], ap[i], bk.y, k23[i]);
            }
        }
        __syncthreads();
    }
    #pragma unroll
    for (int i = 0; i < 2; i++) {
        int gr = m0 + rg * 2 + i;
        if (gr >= M_) continue;
        float4 oq, ok;
        upk2(oq.x, oq.y, q01[i]); upk2(oq.z, oq.w, q23[i]);
        upk2(ok.x, ok.y, k01[i]); upk2(ok.z, ok.w, k23[i]);
        *(float4*)&g_q[(size_t)gr * R_ + cg * 4] = oq;
        *(float4*)&g_k[(size_t)gr * R_ + cg * 4] = ok;
    }
}

// ---------------- K3: scores + signed-abs softmax + dstate ----------------
__device__ __forceinline__ bool edge_valid(int n, int w) {
    if (w < 65) { int p = n + w - WINW; return (p >= 0) && (p < N_); }
    return n > WINW;
}
__device__ __forceinline__ float sgnf(float s) {
    return (s > 0.f) ? 1.f : ((s < 0.f) ? -1.f : 0.f);
}

#define KS_STR 65
__global__ void k_scores() {
    __shared__ float ks[96][KS_STR];
    __shared__ float qs[32][KS_STR];
    __shared__ float k0[64];
    __shared__ float st[97];
    __shared__ float sc[32][68];
    int b  = blockIdx.y;
    int n0 = blockIdx.x * 32;
    int t  = threadIdx.x;
    size_t base = (size_t)b * N_;

    for (int i = t; i < 96 * 64; i += 256) {
        int r = i >> 6, rr = i & 63;
        int g = n0 - WINW + r; g = min(max(g, 0), N_ - 1);
        ks[r][rr] = g_k[(base + g) * R_ + rr];
    }
    for (int i = t; i < 32 * 64; i += 256) {
        int r = i >> 6, rr = i & 63;
        int g = n0 + r; if (g >= N_) g = N_ - 1;
        qs[r][rr] = g_q[(base + g) * R_ + rr];
    }
    if (t < 64) k0[t] = g_k[base * R_ + t];
    if (t < 96) { int g = min(max(n0 - WINW + t, 0), N_ - 1); st[t] = g_state[base + g]; }
    if (t == 96) st[96] = g_state[base];
    __syncthreads();

    {
        int ng2 = t >> 4;
        int wg  = t & 15;
        int i0 = ng2 * 2, w0 = wg * 4;
        float acc[2][4];
        #pragma unroll
        for (int j = 0; j < 2; j++)
            #pragma unroll
            for (int l = 0; l < 4; l++) acc[j][l] = 0.f;
        #pragma unroll 4
        for (int rr = 0; rr < 64; rr++) {
            float q0 = qs[i0][rr];
            float q1 = qs[i0 + 1][rr];
            float kv[5];
            #pragma unroll
            for (int m = 0; m < 5; m++) kv[m] = ks[i0 + w0 + m][rr];
            #pragma unroll
            for (int l = 0; l < 4; l++) {
                acc[0][l] += q0 * kv[l];
                acc[1][l] += q1 * kv[l + 1];
            }
        }
        #pragma unroll
        for (int l = 0; l < 4; l++) {
            sc[i0][w0 + l]     = acc[0][l] * SCALE;
            sc[i0 + 1][w0 + l] = acc[1][l] * SCALE;
        }
    }
    if (t < 64) {
        int i = t >> 1, w = 64 + (t & 1);
        float acc = 0.f;
        if (w == 64) {
            #pragma unroll 8
            for (int rr = 0; rr < 64; rr++) acc += qs[i][rr] * ks[i + 64][rr];
        } else {
            #pragma unroll 8
            for (int rr = 0; rr < 64; rr++) acc += qs[i][rr] * k0[rr];
        }
        sc[i][w] = acc * SCALE;
    }
    __syncthreads();

    int warp = t >> 5, lane = t & 31;
    for (int i = warp; i < 32; i += 8) {
        int n = n0 + i;
        if (n >= N_) continue;
        int w0 = lane, w1 = lane + 32, w2 = (lane < 2) ? 64 + lane : -1;
        float s0 = sc[i][w0], s1 = sc[i][w1];
        float s2 = (w2 >= 0) ? sc[i][w2] : 0.f;
        bool v0 = edge_valid(n, w0);
        bool v1 = edge_valid(n, w1);
        bool v2 = (w2 >= 0) ? edge_valid(n, w2) : false;
        float mx = fmaxf(v0 ? fabsf(s0) : -1e30f,
                   fmaxf(v1 ? fabsf(s1) : -1e30f,
                         v2 ? fabsf(s2) : -1e30f));
        #pragma unroll
        for (int o = 16; o; o >>= 1) mx = fmaxf(mx, __shfl_xor_sync(0xffffffffu, mx, o));
        float e0 = v0 ? expf(fabsf(s0) - mx) : 0.f;
        float e1 = v1 ? expf(fabsf(s1) - mx) : 0.f;
        float e2 = v2 ? expf(fabsf(s2) - mx) : 0.f;
        float sum = e0 + e1 + e2;
        #pragma unroll
        for (int o = 16; o; o >>= 1) sum += __shfl_xor_sync(0xffffffffu, sum, o);
        float invs = 1.f / sum;
        float we0 = sgnf(s0) * e0 * invs;
        float we1 = sgnf(s1) * e1 * invs;
        float we2 = sgnf(s2) * e2 * invs;
        size_t o_ = (base + n) * E_;
        g_we[o_ + w0] = we0;
        g_we[o_ + w1] = we1;
        if (w2 >= 0) g_we[o_ + w2] = we2;
        float ds = we0 * st[i + w0] + we1 * st[i + w1];
        if (lane == 0) ds += we2 * st[i + 64];
        if (lane == 1) ds += we2 * st[96];
        #pragma unroll
        for (int o = 16; o; o >>= 1) ds += __shfl_xor_sync(0xffffffffu, ds, o);
        if (lane == 0) g_dstate[base + n] = ds;
    }
}

// ---------------- K4: dval (R10-best loop + fused residual) ----------------
// block = 64 nodes x 64 feats, 256 threads, thread = 4 nodes x 4 feats
#define DV_NODES 64
#define DV_FEATS 64
#define DV_ROWS  128
#define DV_VSTR  68
#define DV_WSTR  76
// dyn smem: vs[128][68] | wz[64][76] | wa[64] | v0s[64]  = 54784 B
#define DV_SMEM_FLOATS (DV_ROWS*DV_VSTR + DV_NODES*DV_WSTR + DV_NODES + DV_FEATS)

__global__ __launch_bounds__(256, 4) void k_dval() {
    extern __shared__ float sm[];
    float* vs  = sm;                                 // [128][68]
    float* wz  = vs + DV_ROWS * DV_VSTR;             // [64][76], zero-padded
    float* wa  = wz + DV_NODES * DV_WSTR;            // [64]
    float* v0s = wa + DV_NODES;                      // [64]

    int b  = blockIdx.z;
    int dc = blockIdx.y * DV_FEATS;
    int n0 = blockIdx.x * DV_NODES;
    int t  = threadIdx.x;
    size_t base = (size_t)b * N_;

    for (int i = t; i < DV_ROWS * (DV_FEATS / 4); i += 256) {
        int row = i >> 4, c4 = i & 15;
        int g = min(max(n0 - WINW + row, 0), N_ - 1);
        float4 v = *(const float4*)&g_val[(base + g) * D_ + dc + c4 * 4];
        *(float4*)&vs[row * DV_VSTR + c4 * 4] = v;
    }
    for (int i = t; i < DV_NODES * DV_WSTR; i += 256) wz[i] = 0.f;
    if (t < 16) *(float4*)&v0s[t * 4] = *(const float4*)&g_val[base * D_ + dc + t * 4];
    __syncthreads();
    for (int i = t; i < DV_NODES * 65; i += 256) {
        int node = i / 65, w = i % 65;
        int g = n0 + node; if (g >= N_) g = N_ - 1;
        wz[node * DV_WSTR + w + 8] = g_we[(base + g) * E_ + w];
    }
    if (t < DV_NODES) {
        int g = n0 + t; if (g >= N_) g = N_ - 1;
        wa[t] = g_we[(base + g) * E_ + 65];
    }
    __syncthreads();

    int fg = t & 15;          // feat group -> 4 feats
    int ng = t >> 4;          // node group -> 4 nodes
    int i0 = ng * 4;
    int f0 = fg * 4;

    unsigned long long acc01[4], acc23[4];
    #pragma unroll
    for (int j = 0; j < 4; j++) { acc01[j] = 0ull; acc23[j] = 0ull; }

    // r = i0 + rr; weight for node (i0+j) is wz[i0+j][rr - j + 8]
    #pragma unroll 4
    for (int rr = 0; rr < 68; rr++) {
        int r = i0 + rr;
        float w0f = wz[(i0 + 0) * DV_WSTR + rr + 8];
        float w1f = wz[(i0 + 1) * DV_WSTR + rr + 7];
        float w2f = wz[(i0 + 2) * DV_WSTR + rr + 6];
        float w3f = wz[(i0 + 3) * DV_WSTR + rr + 5];
        ulonglong2 vv = *(const ulonglong2*)&vs[r * DV_VSTR + f0];
        unsigned long long wp;
        wp = pk2(w0f, w0f); fma2(acc01[0], wp, vv.x, acc01[0]); fma2(acc23[0], wp, vv.y, acc23[0]);
        wp = pk2(w1f, w1f); fma2(acc01[1], wp, vv.x, acc01[1]); fma2(acc23[1], wp, vv.y, acc23[1]);
        wp = pk2(w2f, w2f); fma2(acc01[2], wp, vv.x, acc01[2]); fma2(acc23[2], wp, vv.y, acc23[2]);
        wp = pk2(w3f, w3f); fma2(acc01[3], wp, vv.x, acc01[3]); fma2(acc23[3], wp, vv.y, acc23[3]);
    }
    // unpack + anchor edge + residual (vs row i0+j+32 = this node's own val) + store
    float4 va = *(const float4*)&v0s[f0];
    #pragma unroll
    for (int j = 0; j < 4; j++) {
        float4 a;
        upk2(a.x, a.y, acc01[j]);
        upk2(a.z, a.w, acc23[j]);
        float wtj = wa[i0 + j];
        float4 rv = *(const float4*)&vs[(i0 + j + 32) * DV_VSTR + f0];
        a.x += wtj * va.x + rv.x; a.y += wtj * va.y + rv.y;
        a.z += wtj * va.z + rv.z; a.w += wtj * va.w + rv.w;
        int n = n0 + i0 + j;
        if (n < N_) {
            *(float4*)&g_dval[(base + n) * D_ + dc + f0] = a;
        }
    }
}

// ---------------- K5: LayerNorm(g_dval = val+dval) + state update ----------------
__global__ void k_ln(const float* __restrict__ lng, const float* __restrict__ lnb,
                     int layer, float* __restrict__ out) {
    __shared__ float sh[8];
    int bn = blockIdx.x;
    int t  = threadIdx.x;
    float* vrow = g_val  + (size_t)bn * D_;
    float* drow = g_dval + (size_t)bn * D_;
    const float* g  = lng + (size_t)layer * D_;
    const float* bt = lnb + (size_t)layer * D_;
    float x0 = drow[t];          // residual already folded in by k_dval
    float x1 = drow[t + 256];
    float m  = blkSum256(x0 + x1, sh) * (1.f / D_);
    float d0 = x0 - m, d1 = x1 - m;
    float var = blkSum256(d0 * d0 + d1 * d1, sh) * (1.f / D_);
    float inv = rsqrtf(var + 1e-5f);
    float y0 = d0 * inv * g[t]       + bt[t];
    float y1 = d1 * inv * g[t + 256] + bt[t + 256];
    float* vdst = out ? (out + M_ + (size_t)bn * D_) : vrow;
    vdst[t]       = y0;
    vdst[t + 256] = y1;
    if (t == 0) {
        float s = g_state[bn] + g_dstate[bn];
        if (out) out[bn] = s;
        else     g_state[bn] = s;
    }
}

// ---------------- host ----------------
extern "C" void kernel_launch(void* const* d_in, const int* in_sizes, int n_in,
                              void* d_out, int out_size) {
    const int*   ids  = (const int*)  d_in[0];
    const float* emb  = (const float*)d_in[1];
    const float* pos  = (const float*)d_in[2];
    const float* aval = (const float*)d_in[3];
    const float* ast  = (const float*)d_in[4];
    const float* ing  = (const float*)d_in[5];
    const float* inb  = (const float*)d_in[6];
    const float* spw  = (const float*)d_in[7];
    const float* spb  = (const float*)d_in[8];
    const float* wq   = (const float*)d_in[9];
    const float* wk   = (const float*)d_in[10];
    const float* lng  = (const float*)d_in[11];
    const float* lnb  = (const float*)d_in[12];
    float* out = (float*)d_out;

    const int dv_smem = DV_SMEM_FLOATS * 4;
    cudaFuncSetAttribute(k_dval, cudaFuncAttributeMaxDynamicSharedMemorySize, dv_smem);

    k_embed<<<M_, 256>>>(ids, emb, pos, aval, ast, ing, inb, spw, spb);
    for (int l = 0; l < L_; l++) {
        k_proj  <<<(M_ + 31) / 32, 256>>>(wq, wk, l);
        k_scores<<<dim3(65, B_), 256>>>();
        k_dval  <<<dim3((N_ + DV_NODES - 1) / DV_NODES, D_ / DV_FEATS, B_), 256, dv_smem>>>();
        k_ln    <<<M_, 256>>>(lng, lnb, l, (l == L_ - 1) ? out : nullptr);
    }
}

// round 14
// speedup vs baseline: 1.0931x; 1.0931x over previous
#include <cuda_runtime.h>
#include <math.h>

#define B_   4
#define S_   2048
#define N_   2049
#define D_   512
#define R_   64
#define L_   2
#define WINW 32
#define E_   66      // 65 window edges + anchor
#define M_   (B_*N_)
#define SCALE 0.125f

// ---------------- scratch (no allocs allowed) ----------------
__device__ float g_val[M_*D_];
__device__ float g_dval[M_*D_];
__device__ float g_q[M_*R_];
__device__ float g_k[M_*R_];
__device__ float g_we[M_*E_];
__device__ float g_state[M_];
__device__ float g_dstate[M_];

// ---------------- packed f32x2 helpers (Blackwell FFMA2) ----------------
__device__ __forceinline__ unsigned long long pk2(float x, float y) {
    unsigned long long r;
    asm("mov.b64 %0, {%1, %2};" : "=l"(r) : "f"(x), "f"(y));
    return r;
}
__device__ __forceinline__ void fma2(unsigned long long& d, unsigned long long a,
                                     unsigned long long b, unsigned long long c) {
    asm("fma.rn.f32x2 %0, %1, %2, %3;" : "=l"(d) : "l"(a), "l"(b), "l"(c));
}
__device__ __forceinline__ void upk2(float& x, float& y, unsigned long long v) {
    asm("mov.b64 {%0, %1}, %2;" : "=f"(x), "=f"(y) : "l"(v));
}

// ---------------- block reduction (256 threads) ----------------
__device__ __forceinline__ float blkSum256(float v, float* sh) {
    int lane = threadIdx.x & 31, w = threadIdx.x >> 5;
    #pragma unroll
    for (int o = 16; o; o >>= 1) v += __shfl_xor_sync(0xffffffffu, v, o);
    if (lane == 0) sh[w] = v;
    __syncthreads();
    if (w == 0) {
        float x = (lane < 8) ? sh[lane] : 0.f;
        #pragma unroll
        for (int o = 4; o; o >>= 1) x += __shfl_xor_sync(0xffffffffu, x, o);
        if (lane == 0) sh[0] = x;
    }
    __syncthreads();
    float r = sh[0];
    __syncthreads();
    return r;
}

// ---------------- K1: embedding + input LN + state proj ----------------
__global__ void k_embed(const int* __restrict__ ids, const float* __restrict__ emb,
                        const float* __restrict__ pos, const float* __restrict__ aval,
                        const float* __restrict__ ast,
                        const float* __restrict__ ing, const float* __restrict__ inb,
                        const float* __restrict__ spw, const float* __restrict__ spb) {
    __shared__ float sh[8];
    int bn = blockIdx.x;
    int b = bn / N_, n = bn % N_;
    float* vrow = g_val + (size_t)bn * D_;
    int t = threadIdx.x;
    if (n == 0) {
        vrow[t]       = aval[t];
        vrow[t + 256] = aval[t + 256];
        if (t == 0) g_state[bn] = ast[0];
        return;
    }
    int id = ids[b * S_ + (n - 1)];
    float x0 = emb[(size_t)id * D_ + t]       + pos[(size_t)(n - 1) * D_ + t];
    float x1 = emb[(size_t)id * D_ + t + 256] + pos[(size_t)(n - 1) * D_ + t + 256];
    float m  = blkSum256(x0 + x1, sh) * (1.f / D_);
    float d0 = x0 - m, d1 = x1 - m;
    float var = blkSum256(d0 * d0 + d1 * d1, sh) * (1.f / D_);
    float inv = rsqrtf(var + 1e-5f);
    float y0 = d0 * inv * ing[t]       + inb[t];
    float y1 = d1 * inv * ing[t + 256] + inb[t + 256];
    vrow[t] = y0; vrow[t + 256] = y1;
    float dp = blkSum256(y0 * spw[t] + y1 * spw[t + 256], sh);
    if (t == 0) g_state[bn] = dp + spb[0];
}

// ---------------- K2: q/k projection  [M,512] @ [512,128], FFMA2 ----------------
// 128 threads, 32-row x 128-col tile, thread = 4 rows x (4 q-cols + 4 k-cols)
__global__ __launch_bounds__(128) void k_proj(const float* __restrict__ wq,
                                              const float* __restrict__ wk, int layer) {
    __shared__ float As[32][36];    // [row][kk]
    __shared__ float Bs[32][132];   // [kk][col] cols 0..63=q, 64..127=k
    int m0 = blockIdx.x * 32;
    const float* wqL = wq + (size_t)layer * D_ * R_;
    const float* wkL = wk + (size_t)layer * D_ * R_;
    int t  = threadIdx.x;
    int cg = t & 15;
    int rg = t >> 4;
    unsigned long long q01[4], q23[4], k01[4], k23[4];
    #pragma unroll
    for (int i = 0; i < 4; i++) { q01[i] = 0ull; q23[i] = 0ull; k01[i] = 0ull; k23[i] = 0ull; }

    for (int kc = 0; kc < D_; kc += 32) {
        #pragma unroll
        for (int i = t; i < 32 * 8; i += 128) {
            int row = i >> 3, kq = (i & 7) * 4;
            int gr = m0 + row; if (gr >= M_) gr = M_ - 1;
            float4 v = *(const float4*)&g_val[(size_t)gr * D_ + kc + kq];
            *(float4*)&As[row][kq] = v;
        }
        #pragma unroll
        for (int i = t; i < 32 * 32; i += 128) {
            int kk = i >> 5, c4 = (i & 31) * 4;
            float4 v;
            if (c4 < 64) v = *(const float4*)&wqL[(size_t)(kc + kk) * R_ + c4];
            else         v = *(const float4*)&wkL[(size_t)(kc + kk) * R_ + (c4 - 64)];
            *(float4*)&Bs[kk][c4] = v;
        }
        __syncthreads();
        #pragma unroll 8
        for (int kk = 0; kk < 32; kk++) {
            unsigned long long ap[4];
            #pragma unroll
            for (int i = 0; i < 4; i++) {
                float av = As[rg * 4 + i][kk];
                ap[i] = pk2(av, av);
            }
            ulonglong2 bq = *(const ulonglong2*)&Bs[kk][cg * 4];
            ulonglong2 bk = *(const ulonglong2*)&Bs[kk][64 + cg * 4];
            #pragma unroll
            for (int i = 0; i < 4; i++) {
                fma2(q01[i], ap[i], bq.x, q01[i]);
                fma2(q23[i], ap[i], bq.y, q23[i]);
                fma2(k01[i], ap[i], bk.x, k01[i]);
                fma2(k23[i], ap[i], bk.y, k23[i]);
            }
        }
        __syncthreads();
    }
    #pragma unroll
    for (int i = 0; i < 4; i++) {
        int gr = m0 + rg * 4 + i;
        if (gr >= M_) continue;
        float4 oq, ok;
        upk2(oq.x, oq.y, q01[i]); upk2(oq.z, oq.w, q23[i]);
        upk2(ok.x, ok.y, k01[i]); upk2(ok.z, ok.w, k23[i]);
        *(float4*)&g_q[(size_t)gr * R_ + cg * 4] = oq;
        *(float4*)&g_k[(size_t)gr * R_ + cg * 4] = ok;
    }
}

// ---------------- K3: scores + signed-abs softmax + dstate (FFMA2) ----------------
__device__ __forceinline__ bool edge_valid(int n, int w) {
    if (w < 65) { int p = n + w - WINW; return (p >= 0) && (p < N_); }
    return n > WINW;
}
__device__ __forceinline__ float sgnf(float s) {
    return (s > 0.f) ? 1.f : ((s < 0.f) ? -1.f : 0.f);
}

#define KS_STR 66   // even stride -> 8B-aligned rr-pairs for LDS.64
__global__ void k_scores() {
    __shared__ float ks[96][KS_STR];
    __shared__ float qs[32][KS_STR];
    __shared__ float k0[64];
    __shared__ float st[97];
    __shared__ float sc[32][68];
    int b  = blockIdx.y;
    int n0 = blockIdx.x * 32;
    int t  = threadIdx.x;
    size_t base = (size_t)b * N_;

    for (int i = t; i < 96 * 64; i += 256) {
        int r = i >> 6, rr = i & 63;
        int g = n0 - WINW + r; g = min(max(g, 0), N_ - 1);
        ks[r][rr] = g_k[(base + g) * R_ + rr];
    }
    for (int i = t; i < 32 * 64; i += 256) {
        int r = i >> 6, rr = i & 63;
        int g = n0 + r; if (g >= N_) g = N_ - 1;
        qs[r][rr] = g_q[(base + g) * R_ + rr];
    }
    if (t < 64) k0[t] = g_k[base * R_ + t];
    if (t < 96) { int g = min(max(n0 - WINW + t, 0), N_ - 1); st[t] = g_state[base + g]; }
    if (t == 96) st[96] = g_state[base];
    __syncthreads();

    // blocked score pass: thread = 2 nodes x 4 edges, rr in packed pairs
    {
        int ng2 = t >> 4;
        int wg  = t & 15;
        int i0 = ng2 * 2, w0 = wg * 4;
        unsigned long long acc2[2][4];
        #pragma unroll
        for (int j = 0; j < 2; j++)
            #pragma unroll
            for (int l = 0; l < 4; l++) acc2[j][l] = 0ull;
        #pragma unroll 4
        for (int rr = 0; rr < 64; rr += 2) {
            unsigned long long q0 = *(const unsigned long long*)&qs[i0][rr];
            unsigned long long q1 = *(const unsigned long long*)&qs[i0 + 1][rr];
            unsigned long long kv[5];
            #pragma unroll
            for (int m = 0; m < 5; m++)
                kv[m] = *(const unsigned long long*)&ks[i0 + w0 + m][rr];
            #pragma unroll
            for (int l = 0; l < 4; l++) {
                fma2(acc2[0][l], q0, kv[l],     acc2[0][l]);
                fma2(acc2[1][l], q1, kv[l + 1], acc2[1][l]);
            }
        }
        #pragma unroll
        for (int l = 0; l < 4; l++) {
            float lo, hi;
            upk2(lo, hi, acc2[0][l]);
            sc[i0][w0 + l] = (lo + hi) * SCALE;
            upk2(lo, hi, acc2[1][l]);
            sc[i0 + 1][w0 + l] = (lo + hi) * SCALE;
        }
    }
    if (t < 64) {
        int i = t >> 1, w = 64 + (t & 1);
        float acc = 0.f;
        if (w == 64) {
            #pragma unroll 8
            for (int rr = 0; rr < 64; rr++) acc += qs[i][rr] * ks[i + 64][rr];
        } else {
            #pragma unroll 8
            for (int rr = 0; rr < 64; rr++) acc += qs[i][rr] * k0[rr];
        }
        sc[i][w] = acc * SCALE;
    }
    __syncthreads();

    int warp = t >> 5, lane = t & 31;
    for (int i = warp; i < 32; i += 8) {
        int n = n0 + i;
        if (n >= N_) continue;
        int w0 = lane, w1 = lane + 32, w2 = (lane < 2) ? 64 + lane : -1;
        float s0 = sc[i][w0], s1 = sc[i][w1];
        float s2 = (w2 >= 0) ? sc[i][w2] : 0.f;
        bool v0 = edge_valid(n, w0);
        bool v1 = edge_valid(n, w1);
        bool v2 = (w2 >= 0) ? edge_valid(n, w2) : false;
        float mx = fmaxf(v0 ? fabsf(s0) : -1e30f,
                   fmaxf(v1 ? fabsf(s1) : -1e30f,
                         v2 ? fabsf(s2) : -1e30f));
        #pragma unroll
        for (int o = 16; o; o >>= 1) mx = fmaxf(mx, __shfl_xor_sync(0xffffffffu, mx, o));
        float e0 = v0 ? expf(fabsf(s0) - mx) : 0.f;
        float e1 = v1 ? expf(fabsf(s1) - mx) : 0.f;
        float e2 = v2 ? expf(fabsf(s2) - mx) : 0.f;
        float sum = e0 + e1 + e2;
        #pragma unroll
        for (int o = 16; o; o >>= 1) sum += __shfl_xor_sync(0xffffffffu, sum, o);
        float invs = 1.f / sum;
        float we0 = sgnf(s0) * e0 * invs;
        float we1 = sgnf(s1) * e1 * invs;
        float we2 = sgnf(s2) * e2 * invs;
        size_t o_ = (base + n) * E_;
        g_we[o_ + w0] = we0;
        g_we[o_ + w1] = we1;
        if (w2 >= 0) g_we[o_ + w2] = we2;
        float ds = we0 * st[i + w0] + we1 * st[i + w1];
        if (lane == 0) ds += we2 * st[i + 64];
        if (lane == 1) ds += we2 * st[96];
        #pragma unroll
        for (int o = 16; o; o >>= 1) ds += __shfl_xor_sync(0xffffffffu, ds, o);
        if (lane == 0) g_dstate[base + n] = ds;
    }
}

// ---------------- K4: dval (R10-best loop + fused residual) ----------------
// block = 64 nodes x 64 feats, 256 threads, thread = 4 nodes x 4 feats
#define DV_NODES 64
#define DV_FEATS 64
#define DV_ROWS  128
#define DV_VSTR  68
#define DV_WSTR  76
// dyn smem: vs[128][68] | wz[64][76] | wa[64] | v0s[64]  = 54784 B
#define DV_SMEM_FLOATS (DV_ROWS*DV_VSTR + DV_NODES*DV_WSTR + DV_NODES + DV_FEATS)

__global__ __launch_bounds__(256, 4) void k_dval() {
    extern __shared__ float sm[];
    float* vs  = sm;                                 // [128][68]
    float* wz  = vs + DV_ROWS * DV_VSTR;             // [64][76], zero-padded
    float* wa  = wz + DV_NODES * DV_WSTR;            // [64]
    float* v0s = wa + DV_NODES;                      // [64]

    int b  = blockIdx.z;
    int dc = blockIdx.y * DV_FEATS;
    int n0 = blockIdx.x * DV_NODES;
    int t  = threadIdx.x;
    size_t base = (size_t)b * N_;

    for (int i = t; i < DV_ROWS * (DV_FEATS / 4); i += 256) {
        int row = i >> 4, c4 = i & 15;
        int g = min(max(n0 - WINW + row, 0), N_ - 1);
        float4 v = *(const float4*)&g_val[(base + g) * D_ + dc + c4 * 4];
        *(float4*)&vs[row * DV_VSTR + c4 * 4] = v;
    }
    for (int i = t; i < DV_NODES * DV_WSTR; i += 256) wz[i] = 0.f;
    if (t < 16) *(float4*)&v0s[t * 4] = *(const float4*)&g_val[base * D_ + dc + t * 4];
    __syncthreads();
    for (int i = t; i < DV_NODES * 65; i += 256) {
        int node = i / 65, w = i % 65;
        int g = n0 + node; if (g >= N_) g = N_ - 1;
        wz[node * DV_WSTR + w + 8] = g_we[(base + g) * E_ + w];
    }
    if (t < DV_NODES) {
        int g = n0 + t; if (g >= N_) g = N_ - 1;
        wa[t] = g_we[(base + g) * E_ + 65];
    }
    __syncthreads();

    int fg = t & 15;          // feat group -> 4 feats
    int ng = t >> 4;          // node group -> 4 nodes
    int i0 = ng * 4;
    int f0 = fg * 4;

    unsigned long long acc01[4], acc23[4];
    #pragma unroll
    for (int j = 0; j < 4; j++) { acc01[j] = 0ull; acc23[j] = 0ull; }

    // r = i0 + rr; weight for node (i0+j) is wz[i0+j][rr - j + 8]
    #pragma unroll 4
    for (int rr = 0; rr < 68; rr++) {
        int r = i0 + rr;
        float w0f = wz[(i0 + 0) * DV_WSTR + rr + 8];
        float w1f = wz[(i0 + 1) * DV_WSTR + rr + 7];
        float w2f = wz[(i0 + 2) * DV_WSTR + rr + 6];
        float w3f = wz[(i0 + 3) * DV_WSTR + rr + 5];
        ulonglong2 vv = *(const ulonglong2*)&vs[r * DV_VSTR + f0];
        unsigned long long wp;
        wp = pk2(w0f, w0f); fma2(acc01[0], wp, vv.x, acc01[0]); fma2(acc23[0], wp, vv.y, acc23[0]);
        wp = pk2(w1f, w1f); fma2(acc01[1], wp, vv.x, acc01[1]); fma2(acc23[1], wp, vv.y, acc23[1]);
        wp = pk2(w2f, w2f); fma2(acc01[2], wp, vv.x, acc01[2]); fma2(acc23[2], wp, vv.y, acc23[2]);
        wp = pk2(w3f, w3f); fma2(acc01[3], wp, vv.x, acc01[3]); fma2(acc23[3], wp, vv.y, acc23[3]);
    }
    // unpack + anchor edge + residual (vs row i0+j+32 = this node's own val) + store
    float4 va = *(const float4*)&v0s[f0];
    #pragma unroll
    for (int j = 0; j < 4; j++) {
        float4 a;
        upk2(a.x, a.y, acc01[j]);
        upk2(a.z, a.w, acc23[j]);
        float wtj = wa[i0 + j];
        float4 rv = *(const float4*)&vs[(i0 + j + 32) * DV_VSTR + f0];
        a.x += wtj * va.x + rv.x; a.y += wtj * va.y + rv.y;
        a.z += wtj * va.z + rv.z; a.w += wtj * va.w + rv.w;
        int n = n0 + i0 + j;
        if (n < N_) {
            *(float4*)&g_dval[(base + n) * D_ + dc + f0] = a;
        }
    }
}

// ---------------- K5: LayerNorm(g_dval = val+dval) + state update ----------------
__global__ void k_ln(const float* __restrict__ lng, const float* __restrict__ lnb,
                     int layer, float* __restrict__ out) {
    __shared__ float sh[8];
    int bn = blockIdx.x;
    int t  = threadIdx.x;
    float* vrow = g_val  + (size_t)bn * D_;
    float* drow = g_dval + (size_t)bn * D_;
    const float* g  = lng + (size_t)layer * D_;
    const float* bt = lnb + (size_t)layer * D_;
    float x0 = drow[t];          // residual already folded in by k_dval
    float x1 = drow[t + 256];
    float m  = blkSum256(x0 + x1, sh) * (1.f / D_);
    float d0 = x0 - m, d1 = x1 - m;
    float var = blkSum256(d0 * d0 + d1 * d1, sh) * (1.f / D_);
    float inv = rsqrtf(var + 1e-5f);
    float y0 = d0 * inv * g[t]       + bt[t];
    float y1 = d1 * inv * g[t + 256] + bt[t + 256];
    float* vdst = out ? (out + M_ + (size_t)bn * D_) : vrow;
    vdst[t]       = y0;
    vdst[t + 256] = y1;
    if (t == 0) {
        float s = g_state[bn] + g_dstate[bn];
        if (out) out[bn] = s;
        else     g_state[bn] = s;
    }
}

// ---------------- host ----------------
extern "C" void kernel_launch(void* const* d_in, const int* in_sizes, int n_in,
                              void* d_out, int out_size) {
    const int*   ids  = (const int*)  d_in[0];
    const float* emb  = (const float*)d_in[1];
    const float* pos  = (const float*)d_in[2];
    const float* aval = (const float*)d_in[3];
    const float* ast  = (const float*)d_in[4];
    const float* ing  = (const float*)d_in[5];
    const float* inb  = (const float*)d_in[6];
    const float* spw  = (const float*)d_in[7];
    const float* spb  = (const float*)d_in[8];
    const float* wq   = (const float*)d_in[9];
    const float* wk   = (const float*)d_in[10];
    const float* lng  = (const float*)d_in[11];
    const float* lnb  = (const float*)d_in[12];
    float* out = (float*)d_out;

    const int dv_smem = DV_SMEM_FLOATS * 4;
    cudaFuncSetAttribute(k_dval, cudaFuncAttributeMaxDynamicSharedMemorySize, dv_smem);

    k_embed<<<M_, 256>>>(ids, emb, pos, aval, ast, ing, inb, spw, spb);
    for (int l = 0; l < L_; l++) {
        k_proj  <<<(M_ + 31) / 32, 128>>>(wq, wk, l);
        k_scores<<<dim3(65, B_), 256>>>();
        k_dval  <<<dim3((N_ + DV_NODES - 1) / DV_NODES, D_ / DV_FEATS, B_), 256, dv_smem>>>();
        k_ln    <<<M_, 256>>>(lng, lnb, l, (l == L_ - 1) ? out : nullptr);
    }
}

// round 16
// speedup vs baseline: 1.1259x; 1.0301x over previous
#include <cuda_runtime.h>
#include <math.h>

#define B_   4
#define S_   2048
#define N_   2049
#define D_   512
#define R_   64
#define L_   2
#define WINW 32
#define E_   66      // 65 window edges + anchor
#define M_   (B_*N_)
#define SCALE 0.125f

// ---------------- scratch (no allocs allowed) ----------------
__device__ float g_val[M_*D_];
__device__ float g_dval[M_*D_];
__device__ float g_q[M_*R_];
__device__ float g_k[M_*R_];
__device__ float g_q2[M_*R_];
__device__ float g_k2[M_*R_];
__device__ float g_we[M_*E_];
__device__ float g_state[M_];
__device__ float g_dstate[M_];

// ---------------- packed f32x2 helpers (Blackwell FFMA2) ----------------
__device__ __forceinline__ unsigned long long pk2(float x, float y) {
    unsigned long long r;
    asm("mov.b64 %0, {%1, %2};" : "=l"(r) : "f"(x), "f"(y));
    return r;
}
__device__ __forceinline__ void fma2(unsigned long long& d, unsigned long long a,
                                     unsigned long long b, unsigned long long c) {
    asm("fma.rn.f32x2 %0, %1, %2, %3;" : "=l"(d) : "l"(a), "l"(b), "l"(c));
}
__device__ __forceinline__ void upk2(float& x, float& y, unsigned long long v) {
    asm("mov.b64 {%0, %1}, %2;" : "=f"(x), "=f"(y) : "l"(v));
}

// ---------------- block reduction (256 threads) ----------------
__device__ __forceinline__ float blkSum256(float v, float* sh) {
    int lane = threadIdx.x & 31, w = threadIdx.x >> 5;
    #pragma unroll
    for (int o = 16; o; o >>= 1) v += __shfl_xor_sync(0xffffffffu, v, o);
    if (lane == 0) sh[w] = v;
    __syncthreads();
    if (w == 0) {
        float x = (lane < 8) ? sh[lane] : 0.f;
        #pragma unroll
        for (int o = 4; o; o >>= 1) x += __shfl_xor_sync(0xffffffffu, x, o);
        if (lane == 0) sh[0] = x;
    }
    __syncthreads();
    float r = sh[0];
    __syncthreads();
    return r;
}

// ---------------- K1: embedding + input LN + state proj ----------------
__global__ void k_embed(const int* __restrict__ ids, const float* __restrict__ emb,
                        const float* __restrict__ pos, const float* __restrict__ aval,
                        const float* __restrict__ ast,
                        const float* __restrict__ ing, const float* __restrict__ inb,
                        const float* __restrict__ spw, const float* __restrict__ spb) {
    __shared__ float sh[8];
    int bn = blockIdx.x;
    int b = bn / N_, n = bn % N_;
    float* vrow = g_val + (size_t)bn * D_;
    int t = threadIdx.x;
    if (n == 0) {
        vrow[t]       = aval[t];
        vrow[t + 256] = aval[t + 256];
        if (t == 0) g_state[bn] = ast[0];
        return;
    }
    int id = ids[b * S_ + (n - 1)];
    float x0 = emb[(size_t)id * D_ + t]       + pos[(size_t)(n - 1) * D_ + t];
    float x1 = emb[(size_t)id * D_ + t + 256] + pos[(size_t)(n - 1) * D_ + t + 256];
    float m  = blkSum256(x0 + x1, sh) * (1.f / D_);
    float d0 = x0 - m, d1 = x1 - m;
    float var = blkSum256(d0 * d0 + d1 * d1, sh) * (1.f / D_);
    float inv = rsqrtf(var + 1e-5f);
    float y0 = d0 * inv * ing[t]       + inb[t];
    float y1 = d1 * inv * ing[t + 256] + inb[t + 256];
    vrow[t] = y0; vrow[t + 256] = y1;
    float dp = blkSum256(y0 * spw[t] + y1 * spw[t + 256], sh);
    if (t == 0) g_state[bn] = dp + spb[0];
}

// ---------------- K2: q/k projection, K-split  [M,512] @ [512,128], FFMA2 ----------------
// grid (257, 2): blockIdx.y = K-half. 128 threads, 32-row x 128-col tile,
// thread = 4 rows x (4 q-cols + 4 k-cols). Halves land in g_q/g_k and g_q2/g_k2.
__global__ __launch_bounds__(128) void k_proj(const float* __restrict__ wq,
                                              const float* __restrict__ wk, int layer) {
    __shared__ float As[32][36];    // [row][kk]
    __shared__ float Bs[32][132];   // [kk][col] cols 0..63=q, 64..127=k
    int m0 = blockIdx.x * 32;
    int kh = blockIdx.y;            // K half: [kh*256, kh*256+256)
    const float* wqL = wq + (size_t)layer * D_ * R_;
    const float* wkL = wk + (size_t)layer * D_ * R_;
    float* qdst = kh ? g_q2 : g_q;
    float* kdst = kh ? g_k2 : g_k;
    int t  = threadIdx.x;
    int cg = t & 15;
    int rg = t >> 4;
    unsigned long long q01[4], q23[4], k01[4], k23[4];
    #pragma unroll
    for (int i = 0; i < 4; i++) { q01[i] = 0ull; q23[i] = 0ull; k01[i] = 0ull; k23[i] = 0ull; }

    int kc0 = kh * 256;
    for (int kc = kc0; kc < kc0 + 256; kc += 32) {
        #pragma unroll
        for (int i = t; i < 32 * 8; i += 128) {
            int row = i >> 3, kq = (i & 7) * 4;
            int gr = m0 + row; if (gr >= M_) gr = M_ - 1;
            float4 v = *(const float4*)&g_val[(size_t)gr * D_ + kc + kq];
            *(float4*)&As[row][kq] = v;
        }
        #pragma unroll
        for (int i = t; i < 32 * 32; i += 128) {
            int kk = i >> 5, c4 = (i & 31) * 4;
            float4 v;
            if (c4 < 64) v = *(const float4*)&wqL[(size_t)(kc + kk) * R_ + c4];
            else         v = *(const float4*)&wkL[(size_t)(kc + kk) * R_ + (c4 - 64)];
            *(float4*)&Bs[kk][c4] = v;
        }
        __syncthreads();
        #pragma unroll 8
        for (int kk = 0; kk < 32; kk++) {
            unsigned long long ap[4];
            #pragma unroll
            for (int i = 0; i < 4; i++) {
                float av = As[rg * 4 + i][kk];
                ap[i] = pk2(av, av);
            }
            ulonglong2 bq = *(const ulonglong2*)&Bs[kk][cg * 4];
            ulonglong2 bk = *(const ulonglong2*)&Bs[kk][64 + cg * 4];
            #pragma unroll
            for (int i = 0; i < 4; i++) {
                fma2(q01[i], ap[i], bq.x, q01[i]);
                fma2(q23[i], ap[i], bq.y, q23[i]);
                fma2(k01[i], ap[i], bk.x, k01[i]);
                fma2(k23[i], ap[i], bk.y, k23[i]);
            }
        }
        __syncthreads();
    }
    #pragma unroll
    for (int i = 0; i < 4; i++) {
        int gr = m0 + rg * 4 + i;
        if (gr >= M_) continue;
        float4 oq, ok;
        upk2(oq.x, oq.y, q01[i]); upk2(oq.z, oq.w, q23[i]);
        upk2(ok.x, ok.y, k01[i]); upk2(ok.z, ok.w, k23[i]);
        *(float4*)&qdst[(size_t)gr * R_ + cg * 4] = oq;
        *(float4*)&kdst[(size_t)gr * R_ + cg * 4] = ok;
    }
}

// ---------------- K3: scores + signed-abs softmax + dstate (FFMA2) ----------------
// staging sums the two proj K-halves (deterministic fixed-order add)
__device__ __forceinline__ bool edge_valid(int n, int w) {
    if (w < 65) { int p = n + w - WINW; return (p >= 0) && (p < N_); }
    return n > WINW;
}
__device__ __forceinline__ float sgnf(float s) {
    return (s > 0.f) ? 1.f : ((s < 0.f) ? -1.f : 0.f);
}

#define KS_STR 66   // even stride -> 8B-aligned rr-pairs for LDS.64
__global__ void k_scores() {
    __shared__ float ks[96][KS_STR];
    __shared__ float qs[32][KS_STR];
    __shared__ float k0[64];
    __shared__ float st[97];
    __shared__ float sc[32][68];
    int b  = blockIdx.y;
    int n0 = blockIdx.x * 32;
    int t  = threadIdx.x;
    size_t base = (size_t)b * N_;

    for (int i = t; i < 96 * 64; i += 256) {
        int r = i >> 6, rr = i & 63;
        int g = n0 - WINW + r; g = min(max(g, 0), N_ - 1);
        size_t idx = (base + g) * R_ + rr;
        ks[r][rr] = g_k[idx] + g_k2[idx];
    }
    for (int i = t; i < 32 * 64; i += 256) {
        int r = i >> 6, rr = i & 63;
        int g = n0 + r; if (g >= N_) g = N_ - 1;
        size_t idx = (base + g) * R_ + rr;
        qs[r][rr] = g_q[idx] + g_q2[idx];
    }
    if (t < 64) k0[t] = g_k[base * R_ + t] + g_k2[base * R_ + t];
    if (t < 96) { int g = min(max(n0 - WINW + t, 0), N_ - 1); st[t] = g_state[base + g]; }
    if (t == 96) st[96] = g_state[base];
    __syncthreads();

    // blocked score pass: thread = 2 nodes x 4 edges, rr in packed pairs
    {
        int ng2 = t >> 4;
        int wg  = t & 15;
        int i0 = ng2 * 2, w0 = wg * 4;
        unsigned long long acc2[2][4];
        #pragma unroll
        for (int j = 0; j < 2; j++)
            #pragma unroll
            for (int l = 0; l < 4; l++) acc2[j][l] = 0ull;
        #pragma unroll 4
        for (int rr = 0; rr < 64; rr += 2) {
            unsigned long long q0 = *(const unsigned long long*)&qs[i0][rr];
            unsigned long long q1 = *(const unsigned long long*)&qs[i0 + 1][rr];
            unsigned long long kv[5];
            #pragma unroll
            for (int m = 0; m < 5; m++)
                kv[m] = *(const unsigned long long*)&ks[i0 + w0 + m][rr];
            #pragma unroll
            for (int l = 0; l < 4; l++) {
                fma2(acc2[0][l], q0, kv[l],     acc2[0][l]);
                fma2(acc2[1][l], q1, kv[l + 1], acc2[1][l]);
            }
        }
        #pragma unroll
        for (int l = 0; l < 4; l++) {
            float lo, hi;
            upk2(lo, hi, acc2[0][l]);
            sc[i0][w0 + l] = (lo + hi) * SCALE;
            upk2(lo, hi, acc2[1][l]);
            sc[i0 + 1][w0 + l] = (lo + hi) * SCALE;
        }
    }
    if (t < 64) {
        int i = t >> 1, w = 64 + (t & 1);
        float acc = 0.f;
        if (w == 64) {
            #pragma unroll 8
            for (int rr = 0; rr < 64; rr++) acc += qs[i][rr] * ks[i + 64][rr];
        } else {
            #pragma unroll 8
            for (int rr = 0; rr < 64; rr++) acc += qs[i][rr] * k0[rr];
        }
        sc[i][w] = acc * SCALE;
    }
    __syncthreads();

    int warp = t >> 5, lane = t & 31;
    for (int i = warp; i < 32; i += 8) {
        int n = n0 + i;
        if (n >= N_) continue;
        int w0 = lane, w1 = lane + 32, w2 = (lane < 2) ? 64 + lane : -1;
        float s0 = sc[i][w0], s1 = sc[i][w1];
        float s2 = (w2 >= 0) ? sc[i][w2] : 0.f;
        bool v0 = edge_valid(n, w0);
        bool v1 = edge_valid(n, w1);
        bool v2 = (w2 >= 0) ? edge_valid(n, w2) : false;
        float mx = fmaxf(v0 ? fabsf(s0) : -1e30f,
                   fmaxf(v1 ? fabsf(s1) : -1e30f,
                         v2 ? fabsf(s2) : -1e30f));
        #pragma unroll
        for (int o = 16; o; o >>= 1) mx = fmaxf(mx, __shfl_xor_sync(0xffffffffu, mx, o));
        float e0 = v0 ? expf(fabsf(s0) - mx) : 0.f;
        float e1 = v1 ? expf(fabsf(s1) - mx) : 0.f;
        float e2 = v2 ? expf(fabsf(s2) - mx) : 0.f;
        float sum = e0 + e1 + e2;
        #pragma unroll
        for (int o = 16; o; o >>= 1) sum += __shfl_xor_sync(0xffffffffu, sum, o);
        float invs = 1.f / sum;
        float we0 = sgnf(s0) * e0 * invs;
        float we1 = sgnf(s1) * e1 * invs;
        float we2 = sgnf(s2) * e2 * invs;
        size_t o_ = (base + n) * E_;
        g_we[o_ + w0] = we0;
        g_we[o_ + w1] = we1;
        if (w2 >= 0) g_we[o_ + w2] = we2;
        float ds = we0 * st[i + w0] + we1 * st[i + w1];
        if (lane == 0) ds += we2 * st[i + 64];
        if (lane == 1) ds += we2 * st[96];
        #pragma unroll
        for (int o = 16; o; o >>= 1) ds += __shfl_xor_sync(0xffffffffu, ds, o);
        if (lane == 0) g_dstate[base + n] = ds;
    }
}

// ---------------- K4: dval (measured-best loop + fused residual) ----------------
// block = 64 nodes x 64 feats, 256 threads, thread = 4 nodes x 4 feats
#define DV_NODES 64
#define DV_FEATS 64
#define DV_ROWS  128
#define DV_VSTR  68
#define DV_WSTR  76
// dyn smem: vs[128][68] | wz[64][76] | wa[64] | v0s[64]  = 54784 B
#define DV_SMEM_FLOATS (DV_ROWS*DV_VSTR + DV_NODES*DV_WSTR + DV_NODES + DV_FEATS)

__global__ __launch_bounds__(256, 4) void k_dval() {
    extern __shared__ float sm[];
    float* vs  = sm;                                 // [128][68]
    float* wz  = vs + DV_ROWS * DV_VSTR;             // [64][76], zero-padded
    float* wa  = wz + DV_NODES * DV_WSTR;            // [64]
    float* v0s = wa + DV_NODES;                      // [64]

    int b  = blockIdx.z;
    int dc = blockIdx.y * DV_FEATS;
    int n0 = blockIdx.x * DV_NODES;
    int t  = threadIdx.x;
    size_t base = (size_t)b * N_;

    for (int i = t; i < DV_ROWS * (DV_FEATS / 4); i += 256) {
        int row = i >> 4, c4 = i & 15;
        int g = min(max(n0 - WINW + row, 0), N_ - 1);
        float4 v = *(const float4*)&g_val[(base + g) * D_ + dc + c4 * 4];
        *(float4*)&vs[row * DV_VSTR + c4 * 4] = v;
    }
    for (int i = t; i < DV_NODES * DV_WSTR; i += 256) wz[i] = 0.f;
    if (t < 16) *(float4*)&v0s[t * 4] = *(const float4*)&g_val[base * D_ + dc + t * 4];
    __syncthreads();
    for (int i = t; i < DV_NODES * 65; i += 256) {
        int node = i / 65, w = i % 65;
        int g = n0 + node; if (g >= N_) g = N_ - 1;
        wz[node * DV_WSTR + w + 8] = g_we[(base + g) * E_ + w];
    }
    if (t < DV_NODES) {
        int g = n0 + t; if (g >= N_) g = N_ - 1;
        wa[t] = g_we[(base + g) * E_ + 65];
    }
    __syncthreads();

    int fg = t & 15;          // feat group -> 4 feats
    int ng = t >> 4;          // node group -> 4 nodes
    int i0 = ng * 4;
    int f0 = fg * 4;

    unsigned long long acc01[4], acc23[4];
    #pragma unroll
    for (int j = 0; j < 4; j++) { acc01[j] = 0ull; acc23[j] = 0ull; }

    // r = i0 + rr; weight for node (i0+j) is wz[i0+j][rr - j + 8]
    #pragma unroll 4
    for (int rr = 0; rr < 68; rr++) {
        int r = i0 + rr;
        float w0f = wz[(i0 + 0) * DV_WSTR + rr + 8];
        float w1f = wz[(i0 + 1) * DV_WSTR + rr + 7];
        float w2f = wz[(i0 + 2) * DV_WSTR + rr + 6];
        float w3f = wz[(i0 + 3) * DV_WSTR + rr + 5];
        ulonglong2 vv = *(const ulonglong2*)&vs[r * DV_VSTR + f0];
        unsigned long long wp;
        wp = pk2(w0f, w0f); fma2(acc01[0], wp, vv.x, acc01[0]); fma2(acc23[0], wp, vv.y, acc23[0]);
        wp = pk2(w1f, w1f); fma2(acc01[1], wp, vv.x, acc01[1]); fma2(acc23[1], wp, vv.y, acc23[1]);
        wp = pk2(w2f, w2f); fma2(acc01[2], wp, vv.x, acc01[2]); fma2(acc23[2], wp, vv.y, acc23[2]);
        wp = pk2(w3f, w3f); fma2(acc01[3], wp, vv.x, acc01[3]); fma2(acc23[3], wp, vv.y, acc23[3]);
    }
    // unpack + anchor edge + residual (vs row i0+j+32 = this node's own val) + store
    float4 va = *(const float4*)&v0s[f0];
    #pragma unroll
    for (int j = 0; j < 4; j++) {
        float4 a;
        upk2(a.x, a.y, acc01[j]);
        upk2(a.z, a.w, acc23[j]);
        float wtj = wa[i0 + j];
        float4 rv = *(const float4*)&vs[(i0 + j + 32) * DV_VSTR + f0];
        a.x += wtj * va.x + rv.x; a.y += wtj * va.y + rv.y;
        a.z += wtj * va.z + rv.z; a.w += wtj * va.w + rv.w;
        int n = n0 + i0 + j;
        if (n < N_) {
            *(float4*)&g_dval[(base + n) * D_ + dc + f0] = a;
        }
    }
}

// ---------------- K5: LayerNorm(g_dval = val+dval) + state update ----------------
__global__ void k_ln(const float* __restrict__ lng, const float* __restrict__ lnb,
                     int layer, float* __restrict__ out) {
    __shared__ float sh[8];
    int bn = blockIdx.x;
    int t  = threadIdx.x;
    float* vrow = g_val  + (size_t)bn * D_;
    float* drow = g_dval + (size_t)bn * D_;
    const float* g  = lng + (size_t)layer * D_;
    const float* bt = lnb + (size_t)layer * D_;
    float x0 = drow[t];          // residual already folded in by k_dval
    float x1 = drow[t + 256];
    float m  = blkSum256(x0 + x1, sh) * (1.f / D_);
    float d0 = x0 - m, d1 = x1 - m;
    float var = blkSum256(d0 * d0 + d1 * d1, sh) * (1.f / D_);
    float inv = rsqrtf(var + 1e-5f);
    float y0 = d0 * inv * g[t]       + bt[t];
    float y1 = d1 * inv * g[t + 256] + bt[t + 256];
    float* vdst = out ? (out + M_ + (size_t)bn * D_) : vrow;
    vdst[t]       = y0;
    vdst[t + 256] = y1;
    if (t == 0) {
        float s = g_state[bn] + g_dstate[bn];
        if (out) out[bn] = s;
        else     g_state[bn] = s;
    }
}

// ---------------- host ----------------
extern "C" void kernel_launch(void* const* d_in, const int* in_sizes, int n_in,
                              void* d_out, int out_size) {
    const int*   ids  = (const int*)  d_in[0];
    const float* emb  = (const float*)d_in[1];
    const float* pos  = (const float*)d_in[2];
    const float* aval = (const float*)d_in[3];
    const float* ast  = (const float*)d_in[4];
    const float* ing  = (const float*)d_in[5];
    const float* inb  = (const float*)d_in[6];
    const float* spw  = (const float*)d_in[7];
    const float* spb  = (const float*)d_in[8];
    const float* wq   = (const float*)d_in[9];
    const float* wk   = (const float*)d_in[10];
    const float* lng  = (const float*)d_in[11];
    const float* lnb  = (const float*)d_in[12];
    float* out = (float*)d_out;

    const int dv_smem = DV_SMEM_FLOATS * 4;
    cudaFuncSetAttribute(k_dval, cudaFuncAttributeMaxDynamicSharedMemorySize, dv_smem);

    k_embed<<<M_, 256>>>(ids, emb, pos, aval, ast, ing, inb, spw, spb);
    for (int l = 0; l < L_; l++) {
        k_proj  <<<dim3((M_ + 31) / 32, 2), 128>>>(wq, wk, l);
        k_scores<<<dim3(65, B_), 256>>>();
        k_dval  <<<dim3((N_ + DV_NODES - 1) / DV_NODES, D_ / DV_FEATS, B_), 256, dv_smem>>>();
        k_ln    <<<M_, 256>>>(lng, lnb, l, (l == L_ - 1) ? out : nullptr);
    }
}